// round 4
// baseline (speedup 1.0000x reference)
#include <cuda_runtime.h>
#include <cstdint>

// Fixed problem geometry (from setup_inputs):
//   fv_label_img : [16, 1, 128, 2048] f32   -> B=16, HW = 262144 = 1<<18
//   fv_pointcloud: [16, 3, 128, 2048] f32
//   bev_h = bev_w = 1024, scale = 1  -> res = 0.1f, half_w = 512
//   out: [16, 1, 1024, 1024] f32
#define HW_SHIFT   18
#define HW         (1 << HW_SHIFT)          // 262144
#define BATCH      16
#define BEV_SHIFT  20
#define BEV_CELLS  (1 << BEV_SHIFT)         // 1024*1024
#define N_POINTS   (BATCH * HW)             // 4,194,304
#define N_OUT      (BATCH * BEV_CELLS)      // 16,777,216

// Priority scratch: per-cell max linear pixel index (+1); 0 == untouched.
__device__ unsigned int g_prio[N_OUT];

// ---------------------------------------------------------------------------
// Kernel 1: out = 255.0f, g_prio = 0 (vectorized 16B stores)
// ---------------------------------------------------------------------------
__global__ void k_init(float4* __restrict__ out)
{
    int i = blockIdx.x * blockDim.x + threadIdx.x;   // 0 .. N_OUT/4 - 1
    out[i] = make_float4(255.0f, 255.0f, 255.0f, 255.0f);
    reinterpret_cast<uint4*>(g_prio)[i] = make_uint4(0u, 0u, 0u, 0u);
}

// ---------------------------------------------------------------------------
// Index math. Must bit-match XLA's lowering of the reference:
//   XLA's algebraic simplifier rewrites  x / 0.1f  ->  x * (1/0.1f), and the
//   f32 round-to-nearest reciprocal of 0.1f is EXACTLY 10.0f. XLA then emits
//   separate rn-multiply and rn-add (no FMA). So the reference computes:
//     x = roundeven(-px * 10.0f + 512.0f)
//     z = roundeven( pz * 10.0f)
//   __fmul_rn/__fadd_rn block nvcc FMA contraction; rintf == roundeven ==
//   jnp.round (TO_NEAREST_EVEN).
// ---------------------------------------------------------------------------
__device__ __forceinline__ bool project(float px, float pz, int& cell)
{
    float xf = rintf(__fadd_rn(__fmul_rn(-px, 10.0f), 512.0f));
    float zf = rintf(__fmul_rn(pz, 10.0f));
    if (xf >= 0.0f && xf < 1024.0f && zf >= 0.0f && zf < 1024.0f) {
        cell = (((int)zf) << 10) | (int)xf;
        return true;
    }
    return false;
}

// ---------------------------------------------------------------------------
// Kernel 2: atomicMax of (pixel_index + 1) into the cell's priority slot.
// Priorities are unique within a batch -> max == last writer in row-major
// update order, matching scatter "last update wins".
// ---------------------------------------------------------------------------
__global__ void k_scatter_prio(const float* __restrict__ pc)
{
    int tid = blockIdx.x * blockDim.x + threadIdx.x;   // 0 .. N_POINTS-1
    int b = tid >> HW_SHIFT;
    int p = tid & (HW - 1);
    const float* base = pc + (size_t)b * (3u << HW_SHIFT);
    float px = base[p];
    float pz = base[(2 << HW_SHIFT) + p];
    int cell;
    if (project(px, pz, cell)) {
        atomicMax(&g_prio[(b << BEV_SHIFT) + cell], (unsigned)p + 1u);
    }
}

// ---------------------------------------------------------------------------
// Kernel 3: each point checks whether it won its cell; the unique winner
// writes its label. Deterministic, race-free.
// ---------------------------------------------------------------------------
__global__ void k_resolve(const float* __restrict__ pc,
                          const float* __restrict__ lab,
                          float* __restrict__ out)
{
    int tid = blockIdx.x * blockDim.x + threadIdx.x;
    int b = tid >> HW_SHIFT;
    int p = tid & (HW - 1);
    const float* base = pc + (size_t)b * (3u << HW_SHIFT);
    float px = base[p];
    float pz = base[(2 << HW_SHIFT) + p];
    int cell;
    if (project(px, pz, cell)) {
        int g = (b << BEV_SHIFT) + cell;
        if (g_prio[g] == (unsigned)p + 1u) {
            out[g] = lab[(b << HW_SHIFT) + p];
        }
    }
}

// ---------------------------------------------------------------------------
extern "C" void kernel_launch(void* const* d_in, const int* in_sizes, int n_in,
                              void* d_out, int out_size)
{
    const float* lab = (const float*)d_in[0];
    const float* pc  = (const float*)d_in[1];
    float* out = (float*)d_out;

    {
        int n = N_OUT / 4;                 // 4M vec4 stores
        k_init<<<n / 256, 256>>>((float4*)out);
    }
    {
        int n = N_POINTS;                  // 4.19M points
        k_scatter_prio<<<n / 256, 256>>>(pc);
        k_resolve<<<n / 256, 256>>>(pc, lab, out);
    }
}

// round 5
// speedup vs baseline: 1.6680x; 1.6680x over previous
#include <cuda_runtime.h>
#include <cstdint>

// Fixed problem geometry (from setup_inputs):
//   fv_label_img : [16, 1, 128, 2048] f32   -> B=16, HW = 262144 = 1<<18
//   fv_pointcloud: [16, 3, 128, 2048] f32
//   bev_h = bev_w = 1024, scale = 1  -> res = 0.1f, half_w = 512
//   out: [16, 1, 1024, 1024] f32
#define HW_SHIFT   18
#define HW         (1 << HW_SHIFT)          // 262144
#define BATCH      16
#define BEV_SHIFT  20
#define BEV_CELLS  (1 << BEV_SHIFT)         // 1024*1024
#define N_POINTS   (BATCH * HW)             // 4,194,304
#define N_OUT      (BATCH * BEV_CELLS)      // 16,777,216
#define EMPTYF     255.0f

// Per-cell winner: max (pixel_index + 1); 0 == untouched.
// INVARIANT: this array is all-zero at every kernel_launch entry.
//   - zero-initialized at module load (.bss)
//   - k_final resets every nonzero word back to 0 each call
// Deterministic: same inputs -> same state -> same work, every call.
__device__ unsigned int g_prio[N_OUT];

// ---------------------------------------------------------------------------
// Projection. Bit-matches XLA's lowering: x/0.1f is algebraically rewritten to
// x * (1/0.1f) where the rn-reciprocal of 0.1f is EXACTLY 10.0f, followed by
// separate rn-mul / rn-add (no FMA). rintf == roundeven == jnp.round.
// ---------------------------------------------------------------------------
__device__ __forceinline__ bool project(float px, float pz, int& cell)
{
    float xf = rintf(__fadd_rn(__fmul_rn(-px, 10.0f), 512.0f));
    float zf = rintf(__fmul_rn(pz, 10.0f));
    if (xf >= 0.0f && xf < 1024.0f && zf >= 0.0f && zf < 1024.0f) {
        cell = (((int)zf) << 10) | (int)xf;
        return true;
    }
    return false;
}

// ---------------------------------------------------------------------------
// Kernel 1: scatter. 4 points per thread (float4 loads of x and z planes).
// atomicMax of (pixel_index + 1): priorities unique within a batch, so max
// == last writer in row-major update order (scatter "last update wins").
// ---------------------------------------------------------------------------
__global__ void k_scatter(const float* __restrict__ pc)
{
    int tid = blockIdx.x * blockDim.x + threadIdx.x;    // 0 .. N_POINTS/4-1
    int g0  = tid << 2;                                  // first point index
    int b   = g0 >> HW_SHIFT;                            // HW % 4 == 0
    int p0  = g0 & (HW - 1);
    const float* base = pc + (size_t)b * (3u << HW_SHIFT);

    float4 px4 = __ldcs((const float4*)(base + p0));
    float4 pz4 = __ldcs((const float4*)(base + (2 << HW_SHIFT) + p0));
    unsigned int* prio_b = g_prio + (b << BEV_SHIFT);

    int cell;
    if (project(px4.x, pz4.x, cell)) atomicMax(&prio_b[cell], (unsigned)p0 + 1u);
    if (project(px4.y, pz4.y, cell)) atomicMax(&prio_b[cell], (unsigned)p0 + 2u);
    if (project(px4.z, pz4.z, cell)) atomicMax(&prio_b[cell], (unsigned)p0 + 3u);
    if (project(px4.w, pz4.w, cell)) atomicMax(&prio_b[cell], (unsigned)p0 + 4u);
}

// ---------------------------------------------------------------------------
// Kernel 2: cell-centric finalize. 4 cells per thread.
//   out[i] = prio[i] ? label[winner] : EMPTY
// and restore the all-zero invariant on g_prio (sparse stores; the touched
// lines are already dirty from the atomics, so the resets are ~free in DRAM).
// ---------------------------------------------------------------------------
__global__ void k_final(const float* __restrict__ lab, float* __restrict__ out)
{
    int tid = blockIdx.x * blockDim.x + threadIdx.x;    // 0 .. N_OUT/4-1
    int i0  = tid << 2;                                  // first cell index
    int b   = i0 >> BEV_SHIFT;                           // BEV_CELLS % 4 == 0
    const float* lab_b = lab + ((size_t)b << HW_SHIFT);

    uint4 v = *(const uint4*)(g_prio + i0);

    float4 o;
    o.x = v.x ? lab_b[v.x - 1u] : EMPTYF;
    o.y = v.y ? lab_b[v.y - 1u] : EMPTYF;
    o.z = v.z ? lab_b[v.z - 1u] : EMPTYF;
    o.w = v.w ? lab_b[v.w - 1u] : EMPTYF;
    __stcs((float4*)(out + i0), o);

    if (v.x | v.y | v.z | v.w) {
        *(uint4*)(g_prio + i0) = make_uint4(0u, 0u, 0u, 0u);
    }
}

// ---------------------------------------------------------------------------
extern "C" void kernel_launch(void* const* d_in, const int* in_sizes, int n_in,
                              void* d_out, int out_size)
{
    const float* lab = (const float*)d_in[0];
    const float* pc  = (const float*)d_in[1];
    float* out = (float*)d_out;

    k_scatter<<<(N_POINTS / 4) / 256, 256>>>(pc);         // 4096 blocks
    k_final  <<<(N_OUT   / 4) / 256, 256>>>(lab, out);    // 16384 blocks
}